// round 4
// baseline (speedup 1.0000x reference)
#include <cuda_runtime.h>

#define NV 23
#define NN 529          // 23*23
#define TV 12
#define ROWLEN 6348     // N*N*T floats per batch
#define ROW4 1587       // ROWLEN/4 = float4s per batch row (= 3*529 exactly)
#define NTHREADS 544    // 17 warps; threads 529..543 idle but sync
#define NBLOCKS 296     // 148 SMs * 2 blocks

__global__ __launch_bounds__(NTHREADS, 2)
void gat_kernel(const float4* __restrict__ flow4,
                const int*    __restrict__ adj,
                const float*  __restrict__ W,
                float*        __restrict__ out,
                int B)
{
    __shared__ float dbuf[2][NN];   // data slice d[m*23+i] for current/next batch
    __shared__ int   adj_s[NN];

    const int tid = threadIdx.x;
    const bool act = (tid < NN);
    int i_idx = 0, k_idx = 0;
    if (act) { i_idx = tid / NV; k_idx = tid - i_idx * NV; }

    // ---- extraction mapping: of float4 indices {t, t+529, t+1058} exactly one
    //      is == 2 (mod 3); its .w is element flat index k=(j-2)/3 of d[m][i].
    const int tm3 = tid % 3;
    const int r_sel = (tm3 == 2) ? 0 : (tm3 == 1 ? 1 : 2);
    const int j_sel = tid + 529 * r_sel;
    const int k_dst = (j_sel - 2) / 3;   // 0..528, bijective over active threads

    // ---- adjacency with forced self-loops ----
    if (act) {
        int a = adj[tid];
        if (i_idx == k_idx) a = 1;
        adj_s[tid] = a;
    }
    __syncthreads();

    // ---- per-thread attention row att[i_idx][k_idx][0..22] in registers ----
    float att[NV];
    if (act) {
        const float* wr = W + tid * NV;
        float mn = 0.0f;                       // = min(min_m W, 0)
        #pragma unroll
        for (int m = 0; m < NV; ++m) {
            att[m] = wr[m];
            mn = fminf(mn, att[m]);
        }
        float s = 0.0f;
        #pragma unroll
        for (int m = 0; m < NV; ++m) {
            float a = (adj_s[k_idx * NV + m] != 0) ? (att[m] - mn) : 0.0f;
            att[m] = a;
            s += a;
        }
        float inv = 1.0f / s;
        #pragma unroll
        for (int m = 0; m < NV; ++m) att[m] *= inv;
    }

    // ---- grid-stride batch loop, coalesced full-row reads, double-buffered ----
    int b = blockIdx.x;
    const int stride = gridDim.x;

    // prologue: stage batch b (3 coalesced float4 loads per thread)
    {
        float4 v = make_float4(0.f, 0.f, 0.f, 0.f);
        if (act && b < B) {
            const float4* row = flow4 + (size_t)b * ROW4;
            float4 v0 = row[tid];
            float4 v1 = row[tid + 529];
            float4 v2 = row[tid + 1058];
            v = (r_sel == 0) ? v0 : (r_sel == 1) ? v1 : v2;
        }
        if (act) dbuf[0][k_dst] = v.w;
    }
    __syncthreads();

    int p = 0;
    for (; b < B; b += stride) {
        const int bn = b + stride;

        // prefetch next batch row, fully coalesced
        float4 w0, w1, w2;
        if (act && bn < B) {
            const float4* row = flow4 + (size_t)bn * ROW4;
            w0 = row[tid];
            w1 = row[tid + 529];
            w2 = row[tid + 1058];
        } else {
            w0 = w1 = w2 = make_float4(0.f, 0.f, 0.f, 0.f);
        }

        // compute x[b, i_idx, k_idx] = sum_m att[m] * d[m, i_idx]
        if (act) {
            const float* d = dbuf[p];
            float acc = 0.0f;
            #pragma unroll
            for (int m = 0; m < NV; ++m)
                acc = fmaf(att[m], d[m * NV + i_idx], acc);
            out[(size_t)b * NN + tid] = acc;     // coalesced
        }

        // stage next batch into the other buffer
        {
            float4 v = (r_sel == 0) ? w0 : (r_sel == 1) ? w1 : w2;
            if (act) dbuf[p ^ 1][k_dst] = v.w;
        }
        __syncthreads();
        p ^= 1;
    }
}

extern "C" void kernel_launch(void* const* d_in, const int* in_sizes, int n_in,
                              void* d_out, int out_size) {
    const float4* flow = (const float4*)d_in[0];  // (B, N, N, T) fp32, 16B-aligned rows
    const int*    adj  = (const int*)   d_in[1];  // (N, N) int32
    const float*  W    = (const float*) d_in[2];  // (N, N, N) fp32
    float*        out  = (float*)d_out;           // (B, N, N, 1) fp32

    const int B = in_sizes[0] / ROWLEN;
    gat_kernel<<<NBLOCKS, NTHREADS>>>(flow, adj, W, out, B);
}

// round 5
// speedup vs baseline: 1.1084x; 1.1084x over previous
#include <cuda_runtime.h>

#define NV 23
#define NN 529          // 23*23
#define TV 12
#define ROWLEN 6348     // N*N*T floats per batch
#define NTHREADS 544    // 17 warps; threads 529..543 idle but sync
#define NBLOCKS 296     // 148 SMs * 2 blocks
#define CHUNK 4         // batches per barrier

__global__ __launch_bounds__(NTHREADS, 2)
void gat_kernel(const float* __restrict__ flow,
                const int*   __restrict__ adj,
                const float* __restrict__ W,
                float*       __restrict__ out,
                int B)
{
    __shared__ float dbuf[2][CHUNK][NN];  // staged slices d[m*23+i]
    __shared__ int   adj_s[NN];

    const int tid = threadIdx.x;
    const bool act = (tid < NN);
    int i_idx = 0, k_idx = 0;
    if (act) { i_idx = tid / NV; k_idx = tid - i_idx * NV; }

    // ---- adjacency with forced self-loops ----
    if (act) {
        int a = adj[tid];
        if (i_idx == k_idx) a = 1;
        adj_s[tid] = a;
    }
    __syncthreads();

    // ---- per-thread attention row att[i_idx][k_idx][0..22] in registers ----
    float att[NV];
    if (act) {
        const float* wr = W + tid * NV;
        float mn = 0.0f;                       // = min(min_m W, 0)
        #pragma unroll
        for (int m = 0; m < NV; ++m) {
            att[m] = wr[m];
            mn = fminf(mn, att[m]);
        }
        float s = 0.0f;
        #pragma unroll
        for (int m = 0; m < NV; ++m) {
            float a = (adj_s[k_idx * NV + m] != 0) ? (att[m] - mn) : 0.0f;
            att[m] = a;
            s += a;
        }
        float inv = 1.0f / s;
        #pragma unroll
        for (int m = 0; m < NV; ++m) att[m] *= inv;
    }

    // ---- chunked grid-stride batch loop, double-buffered, 1 barrier / 4 batches ----
    const int step = gridDim.x * CHUNK;
    int base = blockIdx.x * CHUNK;

    // prologue: stage chunk at 'base'
    if (act) {
        #pragma unroll
        for (int c = 0; c < CHUNK; ++c) {
            const int b = base + c;
            float v = (b < B) ? __ldg(flow + (size_t)b * ROWLEN + tid * TV + (TV - 1))
                              : 0.0f;
            dbuf[0][c][tid] = v;
        }
    }
    __syncthreads();

    int p = 0;
    for (; base < B; base += step) {
        const int nbase = base + step;

        // prefetch next chunk: 4 independent scattered loads per thread
        float nv[CHUNK];
        if (act) {
            #pragma unroll
            for (int c = 0; c < CHUNK; ++c) {
                const int b = nbase + c;
                nv[c] = (b < B) ? __ldg(flow + (size_t)b * ROWLEN + tid * TV + (TV - 1))
                                : 0.0f;
            }
        }

        // compute 4 outputs from staged buffers (overlaps with prefetch latency)
        if (act) {
            #pragma unroll
            for (int c = 0; c < CHUNK; ++c) {
                const int b = base + c;
                if (b < B) {
                    const float* d = dbuf[p][c];
                    float acc = 0.0f;
                    #pragma unroll
                    for (int m = 0; m < NV; ++m)
                        acc = fmaf(att[m], d[m * NV + i_idx], acc);
                    out[(size_t)b * NN + tid] = acc;   // coalesced
                }
            }
        }

        // stage prefetched chunk into the other buffer
        if (act) {
            #pragma unroll
            for (int c = 0; c < CHUNK; ++c)
                dbuf[p ^ 1][c][tid] = nv[c];
        }
        __syncthreads();
        p ^= 1;
    }
}

extern "C" void kernel_launch(void* const* d_in, const int* in_sizes, int n_in,
                              void* d_out, int out_size) {
    const float* flow = (const float*)d_in[0];   // (B, N, N, T) fp32
    const int*   adj  = (const int*)  d_in[1];   // (N, N) int32
    const float* W    = (const float*)d_in[2];   // (N, N, N) fp32
    float*       out  = (float*)d_out;           // (B, N, N, 1) fp32

    const int B = in_sizes[0] / ROWLEN;
    gat_kernel<<<NBLOCKS, NTHREADS>>>(flow, adj, W, out, B);
}